// round 4
// baseline (speedup 1.0000x reference)
#include <cuda_runtime.h>
#include <cuda_bf16.h>
#include <math.h>

// ================= problem constants =================
#define LSEQ 4096
#define EMB 2048
#define KVHEADS 4
#define NSLOTS 32
#define NDIMS 1024
#define NCHUNK 32
#define CLEN 128
#define RHALF 0.70710678118654752f
#define INV_SCALE 0.29730177875068026f   // 1 / 128^0.25
#define EPSF 1e-6f
#define KP 6144                          // K' = 3 * 2048 (hi|lo|hi concat)
#define NKT (KP / 32)                    // 192 k-steps
#define KPITCH 132                       // smem row pitch (floats) in fused kernel

// ================= device scratch =================
__device__ float d_kk[LSEQ * 512];
__device__ float d_vv[LSEQ * 512];
__device__ float d_qq[LSEQ * 2048];
__device__ float d_lend[NCHUNK * NDIMS * NSLOTS];
__device__ float d_carryb[NCHUNK * NDIMS * NSLOTS];
__device__ float d_amat[NCHUNK * NSLOTS * NSLOTS];
__device__ __nv_bfloat16 d_a3[(size_t)LSEQ * KP];      // activation split [M][3K]
__device__ __nv_bfloat16 d_w3[(size_t)5120 * KP];      // all weight splits, n-major
// d_w3 row offsets: wk@0 (512), wv@512, wq@1024 (2048), wd@3072 (2048)

// ================= gate recurrence =================
template <int KEY>
__device__ __forceinline__ void merge_shift(float (&s)[NSLOTS]) {
  s[KEY] = RHALF * (s[KEY] + s[KEY - 1]);
#pragma unroll
  for (int j = KEY - 1; j >= 1; --j) s[j] = s[j - 1];
}

__device__ __forceinline__ void gate_step(float (&s)[NSLOTS], int kdiv) {
  switch (kdiv) {
    case 1: merge_shift<4>(s); break;
    case 2: merge_shift<8>(s); break;
    case 3: merge_shift<12>(s); break;
    case 4: merge_shift<16>(s); break;
    case 5: merge_shift<20>(s); break;
    case 6: merge_shift<24>(s); break;
    case 7: merge_shift<28>(s); break;
    default:
#pragma unroll
      for (int j = 31; j >= 1; --j) s[j] = s[j - 1];
      break;
  }
}

__device__ __forceinline__ int key_div4(int t) { return __ffs(~(t & 1023)); }

// step + store changed slots to smem column (row stride KPITCH floats)
template <int KEY>
__device__ __forceinline__ void step_store(float (&s)[NSLOTS], const float (&kp)[NSLOTS],
                                           float* col, float x) {
  if (KEY < 32) {
    s[KEY] = RHALF * (s[KEY] + s[KEY - 1]);
    col[KEY * KPITCH] = s[KEY] + kp[KEY];
  }
  constexpr int TOP = (KEY < 32) ? KEY : 32;
#pragma unroll
  for (int j = TOP - 1; j >= 1; --j) {
    s[j] = s[j - 1];
    col[j * KPITCH] = s[j] + kp[j];
  }
  s[0] = x;
  col[0] = x + kp[0];
}

// ================= split helpers =================
__device__ __forceinline__ void split_bf16(float x, __nv_bfloat16& h, __nv_bfloat16& l) {
  h = __float2bfloat16_rn(x);
  l = __float2bfloat16_rn(x - __bfloat162float(h));
}

// activation split: src [M][2048] fp32 -> dst [M][6144] bf16 as [hi|lo|hi]
__global__ __launch_bounds__(256) void split_act(const float* __restrict__ src,
                                                 __nv_bfloat16* __restrict__ dst) {
  const int K = EMB;
  int idx = blockIdx.x * 256 + threadIdx.x;
  float4 v = ((const float4*)src)[idx];
  int c = (idx % (K / 4)) * 4;
  int r = idx / (K / 4);
  __nv_bfloat16 h0, l0, h1, l1, h2, l2, h3, l3;
  split_bf16(v.x, h0, l0); split_bf16(v.y, h1, l1);
  split_bf16(v.z, h2, l2); split_bf16(v.w, h3, l3);
  __nv_bfloat162 hA(h0, h1), hB(h2, h3), lA(l0, l1), lB(l2, l3);
  __nv_bfloat16* base = dst + (size_t)r * KP + c;
  *(__nv_bfloat162*)(base) = hA;            *(__nv_bfloat162*)(base + 2) = hB;
  *(__nv_bfloat162*)(base + K) = lA;        *(__nv_bfloat162*)(base + K + 2) = lB;
  *(__nv_bfloat162*)(base + 2 * K) = hA;    *(__nv_bfloat162*)(base + 2 * K + 2) = hB;
}

// weight split + transpose: src [K=2048][N] fp32 -> dst [N][6144] bf16 as [hi|hi|lo]
__global__ __launch_bounds__(256) void split_wt(const float* __restrict__ src,
                                                __nv_bfloat16* __restrict__ dst, int N) {
  const int K = EMB;
  __shared__ float tile[32][33];
  int n0 = blockIdx.x * 32, k0 = blockIdx.y * 32;
  int tx = threadIdx.x & 31, ty = threadIdx.x >> 5;
#pragma unroll
  for (int i = 0; i < 4; i++)
    tile[ty + 8 * i][tx] = src[(size_t)(k0 + ty + 8 * i) * N + n0 + tx];
  __syncthreads();
#pragma unroll
  for (int i = 0; i < 4; i++) {
    int n = n0 + ty + 8 * i;
    int kk = k0 + tx;
    float x = tile[tx][ty + 8 * i];
    __nv_bfloat16 h, l;
    split_bf16(x, h, l);
    __nv_bfloat16* base = dst + (size_t)n * KP;
    base[kk] = h; base[K + kk] = h; base[2 * K + kk] = l;
  }
}

// ================= bf16 tensor-core GEMM =================
#define SPITCH 40
#define STAGEB (128 * SPITCH * 2)

__device__ __forceinline__ void mma16816(float (&c)[4], const unsigned (&a)[4],
                                         unsigned b0, unsigned b1) {
  asm volatile(
      "mma.sync.aligned.m16n8k16.row.col.f32.bf16.bf16.f32 "
      "{%0,%1,%2,%3}, {%4,%5,%6,%7}, {%8,%9}, {%0,%1,%2,%3};"
      : "+f"(c[0]), "+f"(c[1]), "+f"(c[2]), "+f"(c[3])
      : "r"(a[0]), "r"(a[1]), "r"(a[2]), "r"(a[3]), "r"(b0), "r"(b1));
}

#define CP16(dst, src) \
  asm volatile("cp.async.cg.shared.global [%0], [%1], 16;" :: "r"(dst), "l"(src))

__global__ __launch_bounds__(256) void bf16_gemm(
    const __nv_bfloat16* __restrict__ A, const __nv_bfloat16* __restrict__ Bn,
    float* __restrict__ C, int N, float alpha, const float* __restrict__ bias) {
  __shared__ __nv_bfloat16 As[2][128][SPITCH];
  __shared__ __nv_bfloat16 Bs[2][128][SPITCH];

  const int tid = threadIdx.x;
  const int lane = tid & 31, warp = tid >> 5;
  const int wm = (warp & 1) * 64, wn = (warp >> 1) * 32;
  const int g = lane >> 2, t = lane & 3;
  const int crow = blockIdx.y * 128, ccol = blockIdx.x * 128;

  const unsigned sA = (unsigned)__cvta_generic_to_shared(&As[0][0][0]);
  const unsigned sB = (unsigned)__cvta_generic_to_shared(&Bs[0][0][0]);

  const int lr = tid >> 2;
  const int lc = (tid & 3) * 8;
  const __nv_bfloat16* gA = A + (size_t)(crow + lr) * KP + lc;
  const __nv_bfloat16* gB = Bn + (size_t)(ccol + lr) * KP + lc;
  const unsigned dA0 = sA + (lr * SPITCH + lc) * 2;
  const unsigned dA1 = sA + ((lr + 64) * SPITCH + lc) * 2;
  const unsigned dB0 = sB + (lr * SPITCH + lc) * 2;
  const unsigned dB1 = sB + ((lr + 64) * SPITCH + lc) * 2;

  float acc[4][4][4];
#pragma unroll
  for (int i = 0; i < 4; i++)
#pragma unroll
    for (int j = 0; j < 4; j++)
#pragma unroll
      for (int r = 0; r < 4; r++) acc[i][j][r] = 0.f;

  const int a_row = wm + (lane & 15);
  const int a_kof = (lane >> 4) << 3;
  const int b_row = wn + ((lane >> 4) << 3) + (lane & 7);
  const int b_kof = ((lane >> 3) & 1) << 3;

  {
    CP16(dA0, gA); CP16(dA1, gA + (size_t)64 * KP);
    CP16(dB0, gB); CP16(dB1, gB + (size_t)64 * KP);
    asm volatile("cp.async.commit_group;");
  }

  for (int kt = 0; kt < NKT; kt++) {
    const int st = kt & 1;
    if (kt + 1 < NKT) {
      const __nv_bfloat16* pa = gA + (size_t)(kt + 1) * 32;
      const __nv_bfloat16* pb = gB + (size_t)(kt + 1) * 32;
      const unsigned so = (st ^ 1) * STAGEB;
      CP16(dA0 + so, pa); CP16(dA1 + so, pa + (size_t)64 * KP);
      CP16(dB0 + so, pb); CP16(dB1 + so, pb + (size_t)64 * KP);
      asm volatile("cp.async.commit_group;");
      asm volatile("cp.async.wait_group 1;");
    } else {
      asm volatile("cp.async.wait_group 0;");
    }
    __syncthreads();

    const unsigned so = st * STAGEB;
#pragma unroll
    for (int ks = 0; ks < 2; ks++) {
      const int k0 = ks * 16;
      unsigned a[4][4];
#pragma unroll
      for (int i = 0; i < 4; i++) {
        unsigned addr = sA + so + (((a_row + i * 16) * SPITCH) + k0 + a_kof) * 2;
        asm volatile(
            "ldmatrix.sync.aligned.m8n8.x4.shared.b16 {%0,%1,%2,%3}, [%4];"
            : "=r"(a[i][0]), "=r"(a[i][1]), "=r"(a[i][2]), "=r"(a[i][3])
            : "r"(addr));
      }
      unsigned b[4][2];
#pragma unroll
      for (int jj = 0; jj < 2; jj++) {
        unsigned addr = sB + so + (((b_row + jj * 16) * SPITCH) + k0 + b_kof) * 2;
        asm volatile(
            "ldmatrix.sync.aligned.m8n8.x4.shared.b16 {%0,%1,%2,%3}, [%4];"
            : "=r"(b[2 * jj][0]), "=r"(b[2 * jj][1]),
              "=r"(b[2 * jj + 1][0]), "=r"(b[2 * jj + 1][1])
            : "r"(addr));
      }
#pragma unroll
      for (int i = 0; i < 4; i++)
#pragma unroll
        for (int j = 0; j < 4; j++) mma16816(acc[i][j], a[i], b[j][0], b[j][1]);
    }
    __syncthreads();
  }

#pragma unroll
  for (int i = 0; i < 4; i++) {
#pragma unroll
    for (int j = 0; j < 4; j++) {
      int row = crow + wm + i * 16 + g;
      int col = ccol + wn + j * 8 + 2 * t;
      float b0 = bias ? bias[col & 127] : 0.f;
      float b1 = bias ? bias[(col + 1) & 127] : 0.f;
      float2 v0 = make_float2(alpha * acc[i][j][0] + b0, alpha * acc[i][j][1] + b1);
      float2 v1 = make_float2(alpha * acc[i][j][2] + b0, alpha * acc[i][j][3] + b1);
      *(float2*)(C + (size_t)row * N + col) = v0;
      *(float2*)(C + (size_t)(row + 8) * N + col) = v1;
    }
  }
}

// ================= scan pass A: composed chunk maps =================
__global__ void amat_kernel() {
  int c = blockIdx.x;
  int b = threadIdx.x;
  float s[NSLOTS];
#pragma unroll
  for (int j = 0; j < NSLOTS; j++) s[j] = (j == b) ? 1.f : 0.f;
  int t0 = c * CLEN;
  for (int t = t0; t < t0 + CLEN; t++) {
    gate_step(s, key_div4(t));
    s[0] = 0.f;
  }
#pragma unroll
  for (int j = 0; j < NSLOTS; j++) d_amat[(c * NSLOTS + j) * NSLOTS + b] = s[j];
}

// ================= scan pass 1: local scans =================
__global__ __launch_bounds__(128) void scan_pass1() {
  int c = blockIdx.x;
  int g = blockIdx.y * 128 + threadIdx.x;
  const float* src = (g < 512) ? (d_kk + g) : (d_vv + (g - 512));
  float s[NSLOTS];
#pragma unroll
  for (int j = 0; j < NSLOTS; j++) s[j] = 0.f;
  int t0 = c * CLEN;
  for (int t = t0; t < t0 + CLEN; t++) {
    gate_step(s, key_div4(t));
    s[0] = src[(size_t)t * 512];
  }
#pragma unroll
  for (int j = 0; j < NSLOTS; j++) d_lend[(c * NDIMS + g) * NSLOTS + j] = s[j];
}

// ================= scan pass 2: carry propagation =================
__global__ __launch_bounds__(256) void scan_pass2() {
  int g = blockIdx.x * 8 + (threadIdx.x >> 5);
  int j = threadIdx.x & 31;
  float carry = 0.f;
  for (int c = 0; c < NCHUNK; c++) {
    d_carryb[(c * NDIMS + g) * NSLOTS + j] = carry;
    float nc = d_lend[(c * NDIMS + g) * NSLOTS + j];
    const float* arow = &d_amat[(c * NSLOTS + j) * NSLOTS];
#pragma unroll
    for (int i = 0; i < NSLOTS; i++) {
      float ci = __shfl_sync(0xffffffffu, carry, i);
      nc = fmaf(arow[i], ci, nc);
    }
    carry = nc;
  }
}

// ================= fused scan pass 3 + rmsnorm + attention =================
// grid (NCHUNK, KVHEADS), 256 threads: tid<128 -> k-dim d, tid>=128 -> v-dim d.
// Writes attention output directly as bf16 [hi|lo|hi] split into d_a3.
__global__ __launch_bounds__(256) void scan_attn_kernel(
    const float* __restrict__ key_pos, const float* __restrict__ ln_k_w,
    const float* __restrict__ ln_v_w) {
  __shared__ float ksh[NSLOTS][KPITCH];   // [slot][d] (+key_pos), pitch 132
  __shared__ float vsh[NSLOTS][KPITCH];
  __shared__ float qsh[4 * 128];          // q * ln_k_w for 4 heads
  __shared__ float rinv_k[NSLOTS];
  __shared__ float rinv_v[NSLOTS];
  __shared__ float psh[4][NSLOTS];
  __shared__ float lnv[128];

  const int c = blockIdx.x;
  const int kv = blockIdx.y;
  const int tid = threadIdx.x;
  const int d = tid & 127;
  const bool isV = tid >= 128;
  const int warp = tid >> 5;
  const int lane = tid & 31;

  if (isV) lnv[d] = ln_v_w[d];

  // per-thread slot state, seeded from carry
  const int g = isV ? (512 + kv * 128 + d) : (kv * 128 + d);
  float s[NSLOTS];
  const float* carry = &d_carryb[(c * NDIMS + g) * NSLOTS];
#pragma unroll
  for (int j = 0; j < NSLOTS; j++) s[j] = carry[j];

  // key_pos row for k-threads, zeros for v-threads (uniform code path)
  float kp[NSLOTS];
  if (!isV) {
#pragma unroll
    for (int j = 0; j < NSLOTS; j++) kp[j] = key_pos[d * NSLOTS + j];
  } else {
#pragma unroll
    for (int j = 0; j < NSLOTS; j++) kp[j] = 0.f;
  }

  // pre-store current (pre-chunk) state so unchanged rows are always valid
  float* col = isV ? &vsh[0][d] : &ksh[0][d];
#pragma unroll
  for (int j = 0; j < NSLOTS; j++) col[j * KPITCH] = s[j] + kp[j];

  const float* src = isV ? &d_vv[kv * 128 + d] : &d_kk[kv * 128 + d];
  const float* qrow = &d_qq[(size_t)(c * CLEN) * 2048 + kv * 512];
  const float lnk0 = ln_k_w[tid & 127];  // per-thread ln_k_w for its q element(s)

  const int t0 = c * CLEN;
  for (int it = 0; it < CLEN; it++) {
    const int t = t0 + it;
    const int kdiv = key_div4(t);
    const float x = src[(size_t)t * 512];

    // --- phase 1: recurrence step + store changed slots; load q ---
    switch (kdiv) {
      case 1: step_store<4>(s, kp, col, x); break;
      case 2: step_store<8>(s, kp, col, x); break;
      case 3: step_store<12>(s, kp, col, x); break;
      case 4: step_store<16>(s, kp, col, x); break;
      case 5: step_store<20>(s, kp, col, x); break;
      case 6: step_store<24>(s, kp, col, x); break;
      case 7: step_store<28>(s, kp, col, x); break;
      default: step_store<32>(s, kp, col, x); break;
    }
    {
      // 256 threads load 512 q values (float2 each)
      const float2 qv = *(const float2*)&qrow[(size_t)it * 2048 + tid * 2];
      qsh[tid * 2] = qv.x * ln_k_w[(tid * 2) & 127];
      qsh[tid * 2 + 1] = qv.y * ln_k_w[(tid * 2 + 1) & 127];
    }
    __syncthreads();

    // --- phase 2: rms for changed slots (warps 0-3: k, 4-7: v) ---
    const int jm = (it == 0) ? 31 : min(kdiv * 4, 31);
    {
      float(*sh)[KPITCH] = (warp < 4) ? ksh : vsh;
      float* rout = (warp < 4) ? rinv_k : rinv_v;
      const int base = (warp & 3) * 8;
#pragma unroll
      for (int i = 0; i < 8; i++) {
        const int j = base + i;
        if (j <= jm) {
          float x0 = sh[j][lane], x1 = sh[j][lane + 32];
          float x2 = sh[j][lane + 64], x3 = sh[j][lane + 96];
          float ss = fmaf(x0, x0, fmaf(x1, x1, fmaf(x2, x2, x3 * x3)));
#pragma unroll
          for (int off = 16; off; off >>= 1) ss += __shfl_xor_sync(0xffffffffu, ss, off);
          if (lane == 0) rout[j] = rsqrtf(ss * (1.0f / 128.0f) + EPSF);
        }
      }
    }
    __syncthreads();

    // --- phase 3: logits + softmax (warps 0-3 = heads, lane = slot) ---
    if (warp < 4) {
      const int e = lane;
      const float4* qv4 = (const float4*)&qsh[warp * 128];
      const float4* kr4 = (const float4*)&ksh[e][0];
      float acc = 0.f;
#pragma unroll
      for (int i = 0; i < 32; i++) {
        float4 a = qv4[i], b = kr4[i];
        acc = fmaf(a.x, b.x, acc);
        acc = fmaf(a.y, b.y, acc);
        acc = fmaf(a.z, b.z, acc);
        acc = fmaf(a.w, b.w, acc);
      }
      float l = acc * rinv_k[e];
      float m = l;
#pragma unroll
      for (int off = 16; off; off >>= 1) m = fmaxf(m, __shfl_xor_sync(0xffffffffu, m, off));
      float p = expf(l - m);
      float sum = p;
#pragma unroll
      for (int off = 16; off; off >>= 1) sum += __shfl_xor_sync(0xffffffffu, sum, off);
      psh[warp][e] = (p / sum) * rinv_v[e];
    }
    __syncthreads();

    // --- phase 4: AV + direct bf16 split store ---
    {
      const int hx = (tid >> 7) * 2;  // heads {0,1} or {2,3}
      float a0 = 0.f, a1 = 0.f;
#pragma unroll
      for (int e = 0; e < NSLOTS; e++) {
        float vv = vsh[e][d];
        a0 = fmaf(psh[hx][e], vv, a0);
        a1 = fmaf(psh[hx + 1][e], vv, a1);
      }
      const float w = lnv[d];
      a0 *= w; a1 *= w;
      __nv_bfloat16* row = d_a3 + (size_t)t * KP;
      const int c0 = kv * 512 + hx * 128 + d;
      __nv_bfloat16 h, l;
      split_bf16(a0, h, l);
      row[c0] = h; row[c0 + 2048] = l; row[c0 + 4096] = h;
      split_bf16(a1, h, l);
      row[c0 + 128] = h; row[c0 + 128 + 2048] = l; row[c0 + 128 + 4096] = h;
    }
    __syncthreads();
  }
}

// ================= launch =================
extern "C" void kernel_launch(void* const* d_in, const int* in_sizes, int n_in,
                              void* d_out, int out_size) {
  const float* q        = (const float*)d_in[0];
  const float* k        = (const float*)d_in[1];
  const float* v        = (const float*)d_in[2];
  const float* wq       = (const float*)d_in[3];
  const float* wk       = (const float*)d_in[4];
  const float* wv       = (const float*)d_in[5];
  const float* wd       = (const float*)d_in[6];
  const float* key_pos  = (const float*)d_in[7];
  const float* query_pos= (const float*)d_in[8];
  const float* ln_k_w   = (const float*)d_in[9];
  const float* ln_v_w   = (const float*)d_in[10];

  float *p_kk, *p_vv, *p_qq;
  __nv_bfloat16 *p_a3, *p_w3;
  cudaGetSymbolAddress((void**)&p_kk, d_kk);
  cudaGetSymbolAddress((void**)&p_vv, d_vv);
  cudaGetSymbolAddress((void**)&p_qq, d_qq);
  cudaGetSymbolAddress((void**)&p_a3, d_a3);
  cudaGetSymbolAddress((void**)&p_w3, d_w3);

  __nv_bfloat16* w_k = p_w3;
  __nv_bfloat16* w_v = p_w3 + (size_t)512 * KP;
  __nv_bfloat16* w_q = p_w3 + (size_t)1024 * KP;
  __nv_bfloat16* w_d = p_w3 + (size_t)3072 * KP;

  const int actBlocks = LSEQ * EMB / 4 / 256;

  // all weight splits first (launches 1-4) so launch 6 = bf16_gemm for ncu -s 5
  split_wt<<<dim3(512 / 32, EMB / 32), 256>>>(wk, w_k, 512);
  split_wt<<<dim3(512 / 32, EMB / 32), 256>>>(wv, w_v, 512);
  split_wt<<<dim3(2048 / 32, EMB / 32), 256>>>(wq, w_q, 2048);
  split_wt<<<dim3(2048 / 32, EMB / 32), 256>>>(wd, w_d, 2048);

  // k projection
  split_act<<<actBlocks, 256>>>(k, p_a3);
  bf16_gemm<<<dim3(512 / 128, LSEQ / 128), 256>>>(p_a3, w_k, p_kk, 512, INV_SCALE, nullptr);
  // v projection
  split_act<<<actBlocks, 256>>>(v, p_a3);
  bf16_gemm<<<dim3(512 / 128, LSEQ / 128), 256>>>(p_a3, w_v, p_vv, 512, 1.0f, nullptr);
  // q projection (bias = query_pos per 128)
  split_act<<<actBlocks, 256>>>(q, p_a3);
  bf16_gemm<<<dim3(2048 / 128, LSEQ / 128), 256>>>(p_a3, w_q, p_qq, 2048, INV_SCALE, query_pos);

  // chunked linear-recurrence scan (carry setup)
  amat_kernel<<<NCHUNK, 32>>>();
  scan_pass1<<<dim3(NCHUNK, 8), 128>>>();
  scan_pass2<<<128, 256>>>();

  // fused re-scan + rmsnorm + attention -> bf16 split activations
  scan_attn_kernel<<<dim3(NCHUNK, KVHEADS), 256>>>(key_pos, ln_k_w, ln_v_w);

  // output projection
  bf16_gemm<<<dim3(2048 / 128, LSEQ / 128), 256>>>(p_a3, w_d, (float*)d_out, 2048, 1.0f, nullptr);
}